// round 8
// baseline (speedup 1.0000x reference)
#include <cuda_runtime.h>
#include <math.h>
#include <stdint.h>

#define NE 8
#define DDIM 1024
#define IDIM 4096
#define NTOK 8192
#define NROWS (NTOK*2)
#define OUT_ELEMS (NTOK*DDIM)

// ---------------- scratch ----------------
__device__ int   g_cnt[NE];
__device__ int   g_list[NE*NTOK];
__device__ float g_rw[NROWS];
__device__ float g_pp[1024*NE];
__device__ float g_h[NROWS*IDIM];   // tf32-rounded h (gemm2 A operand)
__device__ float g_y[NROWS*DDIM];

// ---------------- helpers ----------------
__device__ __forceinline__ uint32_t totf(float f) {
    uint32_t r;
    asm("cvt.rna.tf32.f32 %0, %1;" : "=r"(r) : "f"(f));
    return r;
}
__device__ __forceinline__ uint4 totf4(float4 v) {
    return make_uint4(totf(v.x), totf(v.y), totf(v.z), totf(v.w));
}
__device__ __forceinline__ void mma8(float* c, const uint32_t* a, uint32_t b0, uint32_t b1) {
    asm volatile(
        "mma.sync.aligned.m16n8k8.row.col.f32.tf32.tf32.f32 "
        "{%0,%1,%2,%3}, {%4,%5,%6,%7}, {%8,%9}, {%0,%1,%2,%3};"
        : "+f"(c[0]), "+f"(c[1]), "+f"(c[2]), "+f"(c[3])
        : "r"(a[0]), "r"(a[1]), "r"(a[2]), "r"(a[3]), "r"(b0), "r"(b1));
}
__device__ __forceinline__ uint32_t f2u(float f) { return __float_as_uint(f); }

// ---------------- small kernels ----------------
__global__ void zero_kernel() { if (threadIdx.x < NE) g_cnt[threadIdx.x] = 0; }

__global__ void __launch_bounds__(256) router_kernel(const float* __restrict__ x,
                                                     const float* __restrict__ wgate) {
    __shared__ float sw[NE*DDIM];
    __shared__ float sprob[8][NE];
    int tid = threadIdx.x;
    for (int i = tid; i < NE*DDIM; i += 256) sw[i] = wgate[i];
    __syncthreads();
    int warp = tid >> 5, lane = tid & 31;
    int n = blockIdx.x * 8 + warp;
    const float* xr = x + (size_t)n * DDIM;
    float xv[32];
#pragma unroll
    for (int i = 0; i < 32; i++) xv[i] = xr[i*32 + lane];
    float p[NE]; float mx = -1e30f;
#pragma unroll
    for (int e = 0; e < NE; e++) {
        float acc = 0.f;
        const float* swe = sw + e*DDIM;
#pragma unroll
        for (int i = 0; i < 32; i++) acc += xv[i] * swe[i*32 + lane];
#pragma unroll
        for (int o = 16; o > 0; o >>= 1) acc += __shfl_xor_sync(0xffffffffu, acc, o);
        p[e] = acc; mx = fmaxf(mx, acc);
    }
    float se = 0.f;
#pragma unroll
    for (int e = 0; e < NE; e++) { p[e] = expf(p[e] - mx); se += p[e]; }
    float inv = 1.f / se;
#pragma unroll
    for (int e = 0; e < NE; e++) p[e] *= inv;
    int e0 = 0;
#pragma unroll
    for (int e = 1; e < NE; e++) if (p[e] > p[e0]) e0 = e;
    int e1 = (e0 == 0) ? 1 : 0;
#pragma unroll
    for (int e = 0; e < NE; e++) if (e != e0 && e != e1 && p[e] > p[e1]) e1 = e;
    if (lane == 0) {
        float w0 = p[e0], w1 = p[e1], s = w0 + w1;
        g_rw[n*2] = w0 / s; g_rw[n*2+1] = w1 / s;
        int p0 = atomicAdd(&g_cnt[e0], 1); g_list[e0*NTOK + p0] = n*2;
        int p1 = atomicAdd(&g_cnt[e1], 1); g_list[e1*NTOK + p1] = n*2 + 1;
#pragma unroll
        for (int e = 0; e < NE; e++) sprob[warp][e] = p[e];
    }
    __syncthreads();
    if (tid == 0) {
#pragma unroll
        for (int e = 0; e < NE; e++) {
            float s = 0.f;
            for (int w = 0; w < 8; w++) s += sprob[w][e];
            g_pp[blockIdx.x*NE + e] = s;
        }
    }
}

// ---------------- GEMM smem geometry ----------------
#define A_ST 36
#define A_FL (128*A_ST)          // 4608 floats

#define B1_ST 72
#define B1_FL (32*B1_ST)         // 2304 floats
#define ST1 (A_FL + 2*B1_FL)     // 9216 floats per stage
#define G1_SMEM (2*ST1*4)        // 73728 B
#define NT1 32

#define B2_ST 136
#define B2_FL (32*B2_ST)         // 4352 floats
#define ST2 (A_FL + B2_FL)       // 8960 floats per stage
#define G2_SMEM (2*ST2*4)        // 71680 B
#define NT2 128

// ---------------- GEMM1: 128 x (64g + 64u) x 1024, prefetch + dbuf + 2 CTA/SM ----------------
__global__ void __launch_bounds__(256, 2) gemm1_mma(const float* __restrict__ x,
                                                    const float* __restrict__ wg,
                                                    const float* __restrict__ wu) {
    extern __shared__ __align__(16) float smf[];
    __shared__ int rows_s[128];

    int e = blockIdx.z;
    int cnt = g_cnt[e];
    int m0 = blockIdx.x * 128;
    if (m0 >= cnt) return;
    int n0 = blockIdx.y * 64;

    int tid = threadIdx.x, wid = tid >> 5, lane = tid & 31;
    if (tid < 128) rows_s[tid] = (m0 + tid < cnt) ? g_list[e*NTOK + m0 + tid] : -1;
    __syncthreads();

    int ar = tid >> 1, ac0 = (tid & 1) * 16;
    int arid = rows_s[ar];
    const float* aptr = (arid >= 0) ? (x + (size_t)(arid >> 1) * DDIM) : nullptr;
    int bk = tid >> 3, bn = tid & 7;
    const float* bgp = wg + ((size_t)e * DDIM + bk) * IDIM + n0;
    const float* bup = wu + ((size_t)e * DDIM + bk) * IDIM + n0;

    int wm = wid & 1, wn = wid >> 1;          // warp tile 64m x 16n per matrix
    int g = lane >> 2, tig = lane & 3;

    float cg[4][2][4], cu[4][2][4];
#pragma unroll
    for (int a = 0; a < 4; a++)
#pragma unroll
        for (int b = 0; b < 2; b++)
#pragma unroll
            for (int c = 0; c < 4; c++) { cg[a][b][c] = 0.f; cu[a][b][c] = 0.f; }

    float4 pa[4], pg[2], pu[2];

#define LOADR1(KT) do {                                                         \
    int kf_ = (KT) * 32;                                                        \
    _Pragma("unroll")                                                           \
    for (int i = 0; i < 4; i++)                                                 \
        pa[i] = aptr ? *(const float4*)(aptr + kf_ + ac0 + i*4)                 \
                     : make_float4(0,0,0,0);                                    \
    _Pragma("unroll")                                                           \
    for (int i = 0; i < 2; i++) {                                               \
        pg[i] = *(const float4*)(bgp + (size_t)kf_ * IDIM + i*32 + bn*4);       \
        pu[i] = *(const float4*)(bup + (size_t)kf_ * IDIM + i*32 + bn*4);       \
    }                                                                           \
} while (0)

#define STS1(SB) do {                                                           \
    float* sb_ = (SB);                                                          \
    _Pragma("unroll")                                                           \
    for (int i = 0; i < 4; i++)                                                 \
        *(uint4*)&sb_[ar*A_ST + ac0 + i*4] = totf4(pa[i]);                      \
    _Pragma("unroll")                                                           \
    for (int i = 0; i < 2; i++) {                                               \
        *(uint4*)&sb_[A_FL + bk*B1_ST + i*32 + bn*4]         = totf4(pg[i]);    \
        *(uint4*)&sb_[A_FL + B1_FL + bk*B1_ST + i*32 + bn*4] = totf4(pu[i]);    \
    }                                                                           \
} while (0)

#define COMP1(SB) do {                                                          \
    const float* As_ = (SB);                                                    \
    const float* Bg_ = (SB) + A_FL;                                             \
    const float* Bu_ = (SB) + A_FL + B1_FL;                                     \
    _Pragma("unroll")                                                           \
    for (int s = 0; s < 4; s++) {                                               \
        uint32_t afr[4][4];                                                     \
        _Pragma("unroll")                                                       \
        for (int mi = 0; mi < 4; mi++) {                                        \
            int r = wm*64 + mi*16 + g, c = s*8 + tig;                           \
            afr[mi][0] = f2u(As_[r*A_ST + c]);                                  \
            afr[mi][1] = f2u(As_[(r+8)*A_ST + c]);                              \
            afr[mi][2] = f2u(As_[r*A_ST + c + 4]);                              \
            afr[mi][3] = f2u(As_[(r+8)*A_ST + c + 4]);                          \
        }                                                                       \
        _Pragma("unroll")                                                       \
        for (int p = 0; p < 2; p++) {                                           \
            int col = wn*16 + p*8 + g;                                          \
            uint32_t g0 = f2u(Bg_[(s*8+tig)*B1_ST + col]);                      \
            uint32_t g1 = f2u(Bg_[(s*8+tig+4)*B1_ST + col]);                    \
            uint32_t u0 = f2u(Bu_[(s*8+tig)*B1_ST + col]);                      \
            uint32_t u1 = f2u(Bu_[(s*8+tig+4)*B1_ST + col]);                    \
            _Pragma("unroll")                                                   \
            for (int mi = 0; mi < 4; mi++) {                                    \
                mma8(cg[mi][p], afr[mi], g0, g1);                               \
                mma8(cu[mi][p], afr[mi], u0, u1);                               \
            }                                                                   \
        }                                                                       \
    }                                                                           \
} while (0)

    LOADR1(0);
    STS1(smf);
    __syncthreads();
    for (int kt = 0; kt < NT1; kt++) {
        bool pf = (kt + 1 < NT1);
        if (pf) LOADR1(kt + 1);
        COMP1(smf + (kt & 1) * ST1);
        if (pf) STS1(smf + ((kt + 1) & 1) * ST1);
        __syncthreads();
    }

    // epilogue: h = silu(gate)*up, tf32-rounded for gemm2
#pragma unroll
    for (int mi = 0; mi < 4; mi++) {
#pragma unroll
        for (int rh = 0; rh < 2; rh++) {
            int m = wm*64 + mi*16 + g + rh*8;
            int rid = rows_s[m];
            if (rid < 0) continue;
            float* hp = g_h + (size_t)rid * IDIM + n0 + wn*16 + 2*tig;
#pragma unroll
            for (int p = 0; p < 2; p++) {
                float gv0 = cg[mi][p][rh*2+0], gv1 = cg[mi][p][rh*2+1];
                float uv0 = cu[mi][p][rh*2+0], uv1 = cu[mi][p][rh*2+1];
                float h0 = gv0 / (1.f + expf(-gv0)) * uv0;
                float h1 = gv1 / (1.f + expf(-gv1)) * uv1;
                *(float2*)(hp + p*8) = make_float2(__uint_as_float(totf(h0)),
                                                   __uint_as_float(totf(h1)));
            }
        }
    }
}

// ---------------- GEMM2: 128 x 128 x 4096, prefetch + dbuf + 2 CTA/SM ----------------
__global__ void __launch_bounds__(256, 2) gemm2_mma(const float* __restrict__ wd) {
    extern __shared__ __align__(16) float smf[];
    __shared__ int rows_s[128];

    int e = blockIdx.z;
    int cnt = g_cnt[e];
    int m0 = blockIdx.x * 128;
    if (m0 >= cnt) return;
    int n0 = blockIdx.y * 128;

    int tid = threadIdx.x, wid = tid >> 5, lane = tid & 31;
    if (tid < 128) rows_s[tid] = (m0 + tid < cnt) ? g_list[e*NTOK + m0 + tid] : -1;
    __syncthreads();

    int ar = tid >> 1, ac0 = (tid & 1) * 16;
    int arid = rows_s[ar];
    const float* aptr = (arid >= 0) ? (g_h + (size_t)arid * IDIM) : nullptr;
    int bk = tid >> 3, bn = tid & 7;
    const float* bp = wd + ((size_t)e * IDIM + bk) * DDIM + n0;

    int wm = wid & 1, wn = wid >> 1;          // warp tile 64m x 32n
    int g = lane >> 2, tig = lane & 3;

    float cc[4][4][4];
#pragma unroll
    for (int a = 0; a < 4; a++)
#pragma unroll
        for (int b = 0; b < 4; b++)
#pragma unroll
            for (int c = 0; c < 4; c++) cc[a][b][c] = 0.f;

    float4 pa[4], pb[4];

#define LOADR2(KT) do {                                                         \
    int kf_ = (KT) * 32;                                                        \
    _Pragma("unroll")                                                           \
    for (int i = 0; i < 4; i++)                                                 \
        pa[i] = aptr ? *(const float4*)(aptr + kf_ + ac0 + i*4)                 \
                     : make_float4(0,0,0,0);                                    \
    _Pragma("unroll")                                                           \
    for (int i = 0; i < 4; i++)                                                 \
        pb[i] = *(const float4*)(bp + (size_t)kf_ * DDIM + i*32 + bn*4);        \
} while (0)

#define STS2(SB) do {                                                           \
    float* sb_ = (SB);                                                          \
    _Pragma("unroll")                                                           \
    for (int i = 0; i < 4; i++)                                                 \
        *(float4*)&sb_[ar*A_ST + ac0 + i*4] = pa[i];   /* g_h already tf32 */   \
    _Pragma("unroll")                                                           \
    for (int i = 0; i < 4; i++)                                                 \
        *(uint4*)&sb_[A_FL + bk*B2_ST + i*32 + bn*4] = totf4(pb[i]);            \
} while (0)

#define COMP2(SB) do {                                                          \
    const float* As_ = (SB);                                                    \
    const float* Bs_ = (SB) + A_FL;                                             \
    _Pragma("unroll")                                                           \
    for (int s = 0; s < 4; s++) {                                               \
        uint32_t afr[4][4];                                                     \
        _Pragma("unroll")                                                       \
        for (int mi = 0; mi < 4; mi++) {                                        \
            int r = wm*64 + mi*16 + g, c = s*8 + tig;                           \
            afr[mi][0] = f2u(As_[r*A_ST + c]);                                  \
            afr[mi][1] = f2u(As_[(r+8)*A_ST + c]);                              \
            afr[mi][2] = f2u(As_[r*A_ST + c + 4]);                              \
            afr[mi][3] = f2u(As_[(r+8)*A_ST + c + 4]);                          \
        }                                                                       \
        _Pragma("unroll")                                                       \
        for (int p = 0; p < 4; p++) {                                           \
            int col = wn*32 + p*8 + g;                                          \
            uint32_t b0 = f2u(Bs_[(s*8+tig)*B2_ST + col]);                      \
            uint32_t b1 = f2u(Bs_[(s*8+tig+4)*B2_ST + col]);                    \
            _Pragma("unroll")                                                   \
            for (int mi = 0; mi < 4; mi++)                                      \
                mma8(cc[mi][p], afr[mi], b0, b1);                               \
        }                                                                       \
    }                                                                           \
} while (0)

    LOADR2(0);
    STS2(smf);
    __syncthreads();
    for (int kt = 0; kt < NT2; kt++) {
        bool pf = (kt + 1 < NT2);
        if (pf) LOADR2(kt + 1);
        COMP2(smf + (kt & 1) * ST2);
        if (pf) STS2(smf + ((kt + 1) & 1) * ST2);
        __syncthreads();
    }

#pragma unroll
    for (int mi = 0; mi < 4; mi++) {
#pragma unroll
        for (int rh = 0; rh < 2; rh++) {
            int m = wm*64 + mi*16 + g + rh*8;
            int rid = rows_s[m];
            if (rid < 0) continue;
            float w = g_rw[rid];
            float* yp = g_y + (size_t)rid * DDIM + n0 + wn*32 + 2*tig;
#pragma unroll
            for (int p = 0; p < 4; p++) {
                float v0 = cc[mi][p][rh*2+0] * w;
                float v1 = cc[mi][p][rh*2+1] * w;
                *(float2*)(yp + p*8) = make_float2(v0, v1);
            }
        }
    }
}

// ---------------- combine + aux ----------------
__global__ void __launch_bounds__(256) combine_kernel(float* __restrict__ out) {
    size_t idx = (size_t)blockIdx.x * 256 + threadIdx.x;
    size_t n = idx >> 8, off = idx & 255;
    const float4* y4 = (const float4*)g_y;
    float4 a = y4[(n*2)     * 256 + off];
    float4 b = y4[(n*2 + 1) * 256 + off];
    ((float4*)out)[idx] = make_float4(a.x+b.x, a.y+b.y, a.z+b.z, a.w+b.w);
}

__global__ void finalize_kernel(float* __restrict__ out, int has_aux) {
    __shared__ float fp[NE];
    int t = threadIdx.x;
    if (t < NE) {
        float s = 0.f;
        for (int b = 0; b < 1024; b++) s += g_pp[b*NE + t];
        float pmean = s / (float)NTOK;
        float f = (float)g_cnt[t] / (float)NROWS;
        fp[t] = f * pmean;
    }
    __syncthreads();
    if (t == 0 && has_aux) {
        float a = 0.f;
        for (int e = 0; e < NE; e++) a += fp[e];
        out[OUT_ELEMS] = 0.02f * (float)NE * a;
    }
}

extern "C" void kernel_launch(void* const* d_in, const int* in_sizes, int n_in,
                              void* d_out, int out_size) {
    const float* x     = (const float*)d_in[0];
    const float* wgate = (const float*)d_in[1];
    const float* wg    = (const float*)d_in[2];
    const float* wu    = (const float*)d_in[3];
    const float* wd    = (const float*)d_in[4];
    float* out = (float*)d_out;

    cudaFuncSetAttribute(gemm1_mma, cudaFuncAttributeMaxDynamicSharedMemorySize, G1_SMEM);
    cudaFuncSetAttribute(gemm2_mma, cudaFuncAttributeMaxDynamicSharedMemorySize, G2_SMEM);

    zero_kernel<<<1, 32>>>();
    router_kernel<<<1024, 256>>>(x, wgate);
    gemm1_mma<<<dim3(64, 64, 8), 256, G1_SMEM>>>(x, wg, wu);
    gemm2_mma<<<dim3(64, 8, 8), 256, G2_SMEM>>>(wd);
    combine_kernel<<<8192, 256>>>(out);
    finalize_kernel<<<1, 32>>>(out, out_size > OUT_ELEMS ? 1 : 0);
}

// round 9
// speedup vs baseline: 1.5024x; 1.5024x over previous
#include <cuda_runtime.h>
#include <cuda_fp16.h>
#include <math.h>
#include <stdint.h>

#define NE 8
#define DDIM 1024
#define IDIM 4096
#define NTOK 8192
#define NROWS (NTOK*2)
#define OUT_ELEMS (NTOK*DDIM)

// ---------------- scratch ----------------
__device__ int   g_cnt[NE];
__device__ int   g_list[NE*NTOK];
__device__ float g_rw[NROWS];
__device__ float g_pp[1024*NE];
__device__ __half g_h[NROWS*IDIM];   // fp16 h (gemm2 A operand)
__device__ float g_y[NROWS*DDIM];

// ---------------- helpers ----------------
__device__ __forceinline__ uint32_t ph2(float a, float b) {
    __half2 h = __floats2half2_rn(a, b);
    return *reinterpret_cast<uint32_t*>(&h);
}
__device__ __forceinline__ uint4 pk8(float4 a, float4 b) {
    return make_uint4(ph2(a.x,a.y), ph2(a.z,a.w), ph2(b.x,b.y), ph2(b.z,b.w));
}
__device__ __forceinline__ void ldm4(uint32_t* r, uint32_t a) {
    asm volatile("ldmatrix.sync.aligned.m8n8.x4.shared.b16 {%0,%1,%2,%3}, [%4];"
        : "=r"(r[0]), "=r"(r[1]), "=r"(r[2]), "=r"(r[3]) : "r"(a));
}
__device__ __forceinline__ void ldm2t(uint32_t* r, uint32_t a) {
    asm volatile("ldmatrix.sync.aligned.m8n8.x2.trans.shared.b16 {%0,%1}, [%2];"
        : "=r"(r[0]), "=r"(r[1]) : "r"(a));
}
__device__ __forceinline__ void mmaf16(float* c, const uint32_t* a, const uint32_t* b) {
    asm volatile(
        "mma.sync.aligned.m16n8k16.row.col.f32.f16.f16.f32 "
        "{%0,%1,%2,%3}, {%4,%5,%6,%7}, {%8,%9}, {%0,%1,%2,%3};"
        : "+f"(c[0]), "+f"(c[1]), "+f"(c[2]), "+f"(c[3])
        : "r"(a[0]), "r"(a[1]), "r"(a[2]), "r"(a[3]), "r"(b[0]), "r"(b[1]));
}
__device__ __forceinline__ uint32_t sgen(const void* p) {
    return (uint32_t)__cvta_generic_to_shared(p);
}

// ---------------- small kernels ----------------
__global__ void zero_kernel() { if (threadIdx.x < NE) g_cnt[threadIdx.x] = 0; }

__global__ void __launch_bounds__(256) router_kernel(const float* __restrict__ x,
                                                     const float* __restrict__ wgate) {
    __shared__ float sw[NE*DDIM];
    __shared__ float sprob[8][NE];
    int tid = threadIdx.x;
    for (int i = tid; i < NE*DDIM; i += 256) sw[i] = wgate[i];
    __syncthreads();
    int warp = tid >> 5, lane = tid & 31;
    int n = blockIdx.x * 8 + warp;
    const float* xr = x + (size_t)n * DDIM;
    float xv[32];
#pragma unroll
    for (int i = 0; i < 32; i++) xv[i] = xr[i*32 + lane];
    float p[NE]; float mx = -1e30f;
#pragma unroll
    for (int e = 0; e < NE; e++) {
        float acc = 0.f;
        const float* swe = sw + e*DDIM;
#pragma unroll
        for (int i = 0; i < 32; i++) acc += xv[i] * swe[i*32 + lane];
#pragma unroll
        for (int o = 16; o > 0; o >>= 1) acc += __shfl_xor_sync(0xffffffffu, acc, o);
        p[e] = acc; mx = fmaxf(mx, acc);
    }
    float se = 0.f;
#pragma unroll
    for (int e = 0; e < NE; e++) { p[e] = expf(p[e] - mx); se += p[e]; }
    float inv = 1.f / se;
#pragma unroll
    for (int e = 0; e < NE; e++) p[e] *= inv;
    int e0 = 0;
#pragma unroll
    for (int e = 1; e < NE; e++) if (p[e] > p[e0]) e0 = e;
    int e1 = (e0 == 0) ? 1 : 0;
#pragma unroll
    for (int e = 0; e < NE; e++) if (e != e0 && e != e1 && p[e] > p[e1]) e1 = e;
    if (lane == 0) {
        float w0 = p[e0], w1 = p[e1], s = w0 + w1;
        g_rw[n*2] = w0 / s; g_rw[n*2+1] = w1 / s;
        int p0 = atomicAdd(&g_cnt[e0], 1); g_list[e0*NTOK + p0] = n*2;
        int p1 = atomicAdd(&g_cnt[e1], 1); g_list[e1*NTOK + p1] = n*2 + 1;
#pragma unroll
        for (int e = 0; e < NE; e++) sprob[warp][e] = p[e];
    }
    __syncthreads();
    if (tid == 0) {
#pragma unroll
        for (int e = 0; e < NE; e++) {
            float s = 0.f;
            for (int w = 0; w < 8; w++) s += sprob[w][e];
            g_pp[blockIdx.x*NE + e] = s;
        }
    }
}

// ---------------- GEMM geometry (fp16 smem) ----------------
#define A_ST2  40            // 128x32 fp16, 80B rows
#define B1_ST2 72            // 32x64 fp16, 144B rows
#define B2_ST2 136           // 32x128 fp16, 272B rows
#define NT1 32
#define NT2 128

// ---------------- GEMM1: 128 x (64g + 64u) x 1024 ----------------
__global__ void __launch_bounds__(256, 2) gemm1_mma(const float* __restrict__ x,
                                                    const float* __restrict__ wg,
                                                    const float* __restrict__ wu) {
    __shared__ __align__(16) __half As[2][128*A_ST2];
    __shared__ __align__(16) __half Bg[2][32*B1_ST2];
    __shared__ __align__(16) __half Bu[2][32*B1_ST2];
    __shared__ int rows_s[128];

    int e = blockIdx.z;
    int cnt = g_cnt[e];
    int m0 = blockIdx.x * 128;
    if (m0 >= cnt) return;
    int n0 = blockIdx.y * 64;

    int tid = threadIdx.x, wid = tid >> 5, lane = tid & 31;
    if (tid < 128) rows_s[tid] = (m0 + tid < cnt) ? g_list[e*NTOK + m0 + tid] : -1;
    __syncthreads();

    int ar = tid >> 1, ach = (tid & 1) * 16;     // A: row, fp16 col base
    int arid = rows_s[ar];
    const float* aptr = (arid >= 0) ? (x + (size_t)(arid >> 1) * DDIM) : nullptr;
    int bk = tid >> 3, bn = tid & 7;             // B: k-row, 8-wide n chunk
    const float* bgp = wg + ((size_t)e * DDIM + bk) * IDIM + n0 + bn*8;
    const float* bup = wu + ((size_t)e * DDIM + bk) * IDIM + n0 + bn*8;

    int wm = wid & 1, wn = wid >> 1;             // warp tile 64m x 16n per matrix
    int g = lane >> 2, tig = lane & 3;
    int q = lane >> 3;
    int rA = (q & 1) * 8 + (lane & 7);
    int cA = (q >> 1) * 8;
    int rB = lane & 15;

    uint32_t as_s = sgen(&As[0][0]), bg_s = sgen(&Bg[0][0]), bu_s = sgen(&Bu[0][0]);
    const uint32_t ABUF = 128*A_ST2*2, BBUF = 32*B1_ST2*2;
    uint32_t abase = as_s + ((wm*64 + rA)*A_ST2 + cA)*2;
    uint32_t gbase = bg_s + (rB*B1_ST2 + wn*16)*2;
    uint32_t ubase = bu_s + (rB*B1_ST2 + wn*16)*2;

    float cg[4][2][4], cu[4][2][4];
#pragma unroll
    for (int a = 0; a < 4; a++)
#pragma unroll
        for (int b = 0; b < 2; b++)
#pragma unroll
            for (int c = 0; c < 4; c++) { cg[a][b][c] = 0.f; cu[a][b][c] = 0.f; }

    uint4 pa0, pa1, pgv, puv;

#define LOADR1(KT) do {                                                         \
    int kf_ = (KT) * 32;                                                        \
    float4 f0, f1, f2, f3;                                                      \
    if (aptr) {                                                                 \
        f0 = *(const float4*)(aptr + kf_ + ach);                                \
        f1 = *(const float4*)(aptr + kf_ + ach + 4);                            \
        f2 = *(const float4*)(aptr + kf_ + ach + 8);                            \
        f3 = *(const float4*)(aptr + kf_ + ach + 12);                           \
    } else { f0 = f1 = f2 = f3 = make_float4(0,0,0,0); }                        \
    pa0 = pk8(f0, f1); pa1 = pk8(f2, f3);                                       \
    float4 g0 = *(const float4*)(bgp + (size_t)kf_ * IDIM);                     \
    float4 g1 = *(const float4*)(bgp + (size_t)kf_ * IDIM + 4);                 \
    float4 u0 = *(const float4*)(bup + (size_t)kf_ * IDIM);                     \
    float4 u1 = *(const float4*)(bup + (size_t)kf_ * IDIM + 4);                 \
    pgv = pk8(g0, g1); puv = pk8(u0, u1);                                       \
} while (0)

#define STS1(B) do {                                                            \
    *(uint4*)&As[B][ar*A_ST2 + ach]     = pa0;                                  \
    *(uint4*)&As[B][ar*A_ST2 + ach + 8] = pa1;                                  \
    *(uint4*)&Bg[B][bk*B1_ST2 + bn*8]   = pgv;                                  \
    *(uint4*)&Bu[B][bk*B1_ST2 + bn*8]   = puv;                                  \
} while (0)

#define COMP1(B) do {                                                           \
    uint32_t ab_ = abase + (B)*ABUF;                                            \
    uint32_t gb_ = gbase + (B)*BBUF;                                            \
    uint32_t ub_ = ubase + (B)*BBUF;                                            \
    _Pragma("unroll")                                                           \
    for (int sp = 0; sp < 2; sp++) {                                            \
        uint32_t af[4][4], gf[2][2], uf[2][2];                                  \
        _Pragma("unroll")                                                       \
        for (int mi = 0; mi < 4; mi++)                                          \
            ldm4(af[mi], ab_ + (mi*16*A_ST2 + sp*16)*2);                        \
        _Pragma("unroll")                                                       \
        for (int p = 0; p < 2; p++) {                                           \
            ldm2t(gf[p], gb_ + (sp*16*B1_ST2 + p*8)*2);                         \
            ldm2t(uf[p], ub_ + (sp*16*B1_ST2 + p*8)*2);                         \
        }                                                                       \
        _Pragma("unroll")                                                       \
        for (int p = 0; p < 2; p++)                                             \
            _Pragma("unroll")                                                   \
            for (int mi = 0; mi < 4; mi++) {                                    \
                mmaf16(cg[mi][p], af[mi], gf[p]);                               \
                mmaf16(cu[mi][p], af[mi], uf[p]);                               \
            }                                                                   \
    }                                                                           \
} while (0)

    LOADR1(0);
    STS1(0);
    __syncthreads();
    for (int kt = 0; kt < NT1; kt++) {
        bool pf = (kt + 1 < NT1);
        if (pf) LOADR1(kt + 1);
        COMP1(kt & 1);
        if (pf) STS1((kt + 1) & 1);
        __syncthreads();
    }

    // epilogue: h = silu(gate)*up -> fp16
#pragma unroll
    for (int mi = 0; mi < 4; mi++) {
#pragma unroll
        for (int rh = 0; rh < 2; rh++) {
            int m = wm*64 + mi*16 + g + rh*8;
            int rid = rows_s[m];
            if (rid < 0) continue;
            __half2* hp = (__half2*)(g_h + (size_t)rid * IDIM + n0 + wn*16 + 2*tig);
#pragma unroll
            for (int p = 0; p < 2; p++) {
                float gv0 = cg[mi][p][rh*2+0], gv1 = cg[mi][p][rh*2+1];
                float uv0 = cu[mi][p][rh*2+0], uv1 = cu[mi][p][rh*2+1];
                float h0 = gv0 / (1.f + expf(-gv0)) * uv0;
                float h1 = gv1 / (1.f + expf(-gv1)) * uv1;
                hp[p*4] = __floats2half2_rn(h0, h1);
            }
        }
    }
}

// ---------------- GEMM2: 128 x 128 x 4096 ----------------
__global__ void __launch_bounds__(256, 2) gemm2_mma(const float* __restrict__ wd) {
    __shared__ __align__(16) __half As[2][128*A_ST2];
    __shared__ __align__(16) __half Bs[2][32*B2_ST2];
    __shared__ int rows_s[128];

    int e = blockIdx.z;
    int cnt = g_cnt[e];
    int m0 = blockIdx.x * 128;
    if (m0 >= cnt) return;
    int n0 = blockIdx.y * 128;

    int tid = threadIdx.x, wid = tid >> 5, lane = tid & 31;
    if (tid < 128) rows_s[tid] = (m0 + tid < cnt) ? g_list[e*NTOK + m0 + tid] : -1;
    __syncthreads();

    int ar = tid >> 1, ach = (tid & 1) * 16;
    int arid = rows_s[ar];
    const __half* aptr = (arid >= 0) ? (g_h + (size_t)arid * IDIM) : nullptr;
    int bk = tid >> 3, bn = tid & 7;             // 16-wide n chunk
    const float* bp = wd + ((size_t)e * IDIM + bk) * DDIM + n0 + bn*16;

    int wm = wid & 1, wn = wid >> 1;             // warp tile 64m x 32n
    int g = lane >> 2, tig = lane & 3;
    int q = lane >> 3;
    int rA = (q & 1) * 8 + (lane & 7);
    int cA = (q >> 1) * 8;
    int rB = lane & 15;

    uint32_t as_s = sgen(&As[0][0]), bs_s = sgen(&Bs[0][0]);
    const uint32_t ABUF = 128*A_ST2*2, BBUF = 32*B2_ST2*2;
    uint32_t abase = as_s + ((wm*64 + rA)*A_ST2 + cA)*2;
    uint32_t bbase = bs_s + (rB*B2_ST2 + wn*32)*2;

    float cc[4][4][4];
#pragma unroll
    for (int a = 0; a < 4; a++)
#pragma unroll
        for (int b = 0; b < 4; b++)
#pragma unroll
            for (int c = 0; c < 4; c++) cc[a][b][c] = 0.f;

    uint4 pa0, pa1, pb0, pb1;

#define LOADR2(KT) do {                                                         \
    int kf_ = (KT) * 32;                                                        \
    if (aptr) {                                                                 \
        pa0 = *(const uint4*)(aptr + kf_ + ach);                                \
        pa1 = *(const uint4*)(aptr + kf_ + ach + 8);                            \
    } else { pa0 = make_uint4(0,0,0,0); pa1 = pa0; }                            \
    float4 b0 = *(const float4*)(bp + (size_t)kf_ * DDIM);                      \
    float4 b1 = *(const float4*)(bp + (size_t)kf_ * DDIM + 4);                  \
    float4 b2 = *(const float4*)(bp + (size_t)kf_ * DDIM + 8);                  \
    float4 b3 = *(const float4*)(bp + (size_t)kf_ * DDIM + 12);                 \
    pb0 = pk8(b0, b1); pb1 = pk8(b2, b3);                                       \
} while (0)

#define STS2(B) do {                                                            \
    *(uint4*)&As[B][ar*A_ST2 + ach]       = pa0;                                \
    *(uint4*)&As[B][ar*A_ST2 + ach + 8]   = pa1;                                \
    *(uint4*)&Bs[B][bk*B2_ST2 + bn*16]     = pb0;                               \
    *(uint4*)&Bs[B][bk*B2_ST2 + bn*16 + 8] = pb1;                               \
} while (0)

#define COMP2(B) do {                                                           \
    uint32_t ab_ = abase + (B)*ABUF;                                            \
    uint32_t bb_ = bbase + (B)*BBUF;                                            \
    _Pragma("unroll")                                                           \
    for (int sp = 0; sp < 2; sp++) {                                            \
        uint32_t af[4][4], bf[4][2];                                            \
        _Pragma("unroll")                                                       \
        for (int mi = 0; mi < 4; mi++)                                          \
            ldm4(af[mi], ab_ + (mi*16*A_ST2 + sp*16)*2);                        \
        _Pragma("unroll")                                                       \
        for (int p = 0; p < 4; p++)                                             \
            ldm2t(bf[p], bb_ + (sp*16*B2_ST2 + p*8)*2);                         \
        _Pragma("unroll")                                                       \
        for (int p = 0; p < 4; p++)                                             \
            _Pragma("unroll")                                                   \
            for (int mi = 0; mi < 4; mi++)                                      \
                mmaf16(cc[mi][p], af[mi], bf[p]);                               \
    }                                                                           \
} while (0)

    LOADR2(0);
    STS2(0);
    __syncthreads();
    for (int kt = 0; kt < NT2; kt++) {
        bool pf = (kt + 1 < NT2);
        if (pf) LOADR2(kt + 1);
        COMP2(kt & 1);
        if (pf) STS2((kt + 1) & 1);
        __syncthreads();
    }

#pragma unroll
    for (int mi = 0; mi < 4; mi++) {
#pragma unroll
        for (int rh = 0; rh < 2; rh++) {
            int m = wm*64 + mi*16 + g + rh*8;
            int rid = rows_s[m];
            if (rid < 0) continue;
            float w = g_rw[rid];
            float* yp = g_y + (size_t)rid * DDIM + n0 + wn*32 + 2*tig;
#pragma unroll
            for (int p = 0; p < 4; p++) {
                float v0 = cc[mi][p][rh*2+0] * w;
                float v1 = cc[mi][p][rh*2+1] * w;
                *(float2*)(yp + p*8) = make_float2(v0, v1);
            }
        }
    }
}

// ---------------- combine + aux ----------------
__global__ void __launch_bounds__(256) combine_kernel(float* __restrict__ out) {
    size_t idx = (size_t)blockIdx.x * 256 + threadIdx.x;
    size_t n = idx >> 8, off = idx & 255;
    const float4* y4 = (const float4*)g_y;
    float4 a = y4[(n*2)     * 256 + off];
    float4 b = y4[(n*2 + 1) * 256 + off];
    ((float4*)out)[idx] = make_float4(a.x+b.x, a.y+b.y, a.z+b.z, a.w+b.w);
}

__global__ void finalize_kernel(float* __restrict__ out, int has_aux) {
    __shared__ float fp[NE];
    int t = threadIdx.x;
    if (t < NE) {
        float s = 0.f;
        for (int b = 0; b < 1024; b++) s += g_pp[b*NE + t];
        float pmean = s / (float)NTOK;
        float f = (float)g_cnt[t] / (float)NROWS;
        fp[t] = f * pmean;
    }
    __syncthreads();
    if (t == 0 && has_aux) {
        float a = 0.f;
        for (int e = 0; e < NE; e++) a += fp[e];
        out[OUT_ELEMS] = 0.02f * (float)NE * a;
    }
}

extern "C" void kernel_launch(void* const* d_in, const int* in_sizes, int n_in,
                              void* d_out, int out_size) {
    const float* x     = (const float*)d_in[0];
    const float* wgate = (const float*)d_in[1];
    const float* wg    = (const float*)d_in[2];
    const float* wu    = (const float*)d_in[3];
    const float* wd    = (const float*)d_in[4];
    float* out = (float*)d_out;

    zero_kernel<<<1, 32>>>();
    router_kernel<<<1024, 256>>>(x, wgate);
    gemm1_mma<<<dim3(64, 64, 8), 256>>>(x, wg, wu);
    gemm2_mma<<<dim3(64, 8, 8), 256>>>(wd);
    combine_kernel<<<8192, 256>>>(out);
    finalize_kernel<<<1, 32>>>(out, out_size > OUT_ELEMS ? 1 : 0);
}